// round 1
// baseline (speedup 1.0000x reference)
#include <cuda_runtime.h>
#include <math.h>

#define BB 4
#define LL 2048
#define DD 1024
#define HH 16
#define HDIM 64
#define NROWS (BB * LL)   // 8192

// ---------------- scratch (device globals; no allocation allowed) ----------------
__device__ float g_h[NROWS * DD];     // LN(x)
__device__ float g_q[NROWS * DD];     // (B,H,L,HD)
__device__ float g_k[NROWS * DD];
__device__ float g_v[NROWS * DD];
__device__ float g_att[NROWS * DD];   // attention out, (B,L,D)
__device__ float g_y[NROWS * DD];     // O-proj out
__device__ unsigned char g_mask[NROWS];

// ---------------- padding-mask dtype detection + canonicalization ----------------
// bool mask (B,L): may arrive as uint8 / int32 / float32. Detect from first
// NROWS bytes (safe to read under every candidate dtype):
//   int32 0/1  -> nonzero bytes only at j%4==0
//   float32 1.0f -> nonzero bytes at j%4==2(0x80),3(0x3f); never at j%4==0
//   uint8     -> padding tail of each row always contains a position ==3 mod 4
__global__ void convert_mask_kernel(const unsigned char* __restrict__ pm) {
    __shared__ int fz0, fz3;
    int tid = threadIdx.x;
    if (tid == 0) { fz0 = 0; fz3 = 0; }
    __syncthreads();
    int z0 = 0, z3 = 0;
    for (int j = tid; j < NROWS; j += blockDim.x) {
        unsigned char v = pm[j];
        if (v) {
            if ((j & 3) == 0) z0 = 1;
            if ((j & 3) == 3) z3 = 1;
        }
    }
    if (z0) atomicOr(&fz0, 1);
    if (z3) atomicOr(&fz3, 1);
    __syncthreads();
    int mode; // 0=all-zero, 1=uint8, 2=float32, 3=int32
    if (!fz3) mode = fz0 ? 3 : 0;
    else      mode = fz0 ? 1 : 2;
    for (int i = tid; i < NROWS; i += blockDim.x) {
        unsigned char r;
        if (mode == 0)      r = 0;
        else if (mode == 1) r = (pm[i] != 0);
        else if (mode == 2) r = (((const float*)pm)[i] != 0.0f);
        else                r = (((const int*)pm)[i] != 0);
        g_mask[i] = r;
    }
}

// ---------------- LayerNorm (optionally fused residual add) ----------------
// one block per row; 256 threads x 4 elems = 1024
__global__ void ln_kernel(const float* __restrict__ x, const float* __restrict__ res,
                          const float* __restrict__ gamma, const float* __restrict__ beta,
                          float* __restrict__ out) {
    int row = blockIdx.x;
    int tid = threadIdx.x;
    const float4* xr = (const float4*)(x + (size_t)row * DD);
    float4 v = xr[tid];
    if (res) {
        const float4* rr = (const float4*)(res + (size_t)row * DD);
        float4 r2 = rr[tid];
        v.x += r2.x; v.y += r2.y; v.z += r2.z; v.w += r2.w;
    }
    float s  = v.x + v.y + v.z + v.w;
    float ss = v.x * v.x + v.y * v.y + v.z * v.z + v.w * v.w;
    for (int off = 16; off > 0; off >>= 1) {
        s  += __shfl_down_sync(0xffffffffu, s, off);
        ss += __shfl_down_sync(0xffffffffu, ss, off);
    }
    __shared__ float rs[8], rss[8];
    __shared__ float s_mu, s_rsig;
    int wid = tid >> 5, lane = tid & 31;
    if (lane == 0) { rs[wid] = s; rss[wid] = ss; }
    __syncthreads();
    if (tid == 0) {
        float S = 0.f, SS = 0.f;
        #pragma unroll
        for (int i = 0; i < 8; i++) { S += rs[i]; SS += rss[i]; }
        float mu  = S * (1.0f / DD);
        float var = SS * (1.0f / DD) - mu * mu;
        s_mu = mu;
        s_rsig = rsqrtf(var + 1e-5f);
    }
    __syncthreads();
    float mu = s_mu, rsig = s_rsig;
    float4 gv = ((const float4*)gamma)[tid];
    float4 bv = ((const float4*)beta)[tid];
    float4 o;
    o.x = (v.x - mu) * rsig * gv.x + bv.x;
    o.y = (v.y - mu) * rsig * gv.y + bv.y;
    o.z = (v.z - mu) * rsig * gv.z + bv.z;
    o.w = (v.w - mu) * rsig * gv.w + bv.w;
    ((float4*)(out + (size_t)row * DD))[tid] = o;
}

// ---------------- NT GEMM: C[i,j] = sum_k A[i,k]*B[j,k] + bias[j] ----------------
// BM=BN=128, BK=16, 256 threads, 8x8 per thread.
// MODE 0: C row-major [M,N].  MODE 1: scatter to (B,H,L,HD) q/k/v layout.
template <int MODE>
__global__ void gemm_nt(const float* __restrict__ A, const float* __restrict__ Bm,
                        const float* __restrict__ bias, float* __restrict__ C,
                        int M, int N, int K) {
    __shared__ float As[16][128];
    __shared__ float Bs[16][128];
    int tid = threadIdx.x;
    int bx = blockIdx.x;            // N tile
    int by = blockIdx.y;            // M tile
    int ty = tid >> 4, tx = tid & 15;
    int rowA0 = by * 128, colB0 = bx * 128;

    float acc[8][8];
    #pragma unroll
    for (int i = 0; i < 8; i++)
        #pragma unroll
        for (int j = 0; j < 8; j++) acc[i][j] = 0.f;

    for (int k0 = 0; k0 < K; k0 += 16) {
        #pragma unroll
        for (int i = 0; i < 2; i++) {
            int idx = tid * 2 + i;          // 0..511
            int r = idx >> 2;               // 0..127
            int kv = (idx & 3) * 4;         // 0,4,8,12
            float4 a = *(const float4*)&A[(size_t)(rowA0 + r) * K + k0 + kv];
            As[kv + 0][r] = a.x; As[kv + 1][r] = a.y;
            As[kv + 2][r] = a.z; As[kv + 3][r] = a.w;
            float4 b = *(const float4*)&Bm[(size_t)(colB0 + r) * K + k0 + kv];
            Bs[kv + 0][r] = b.x; Bs[kv + 1][r] = b.y;
            Bs[kv + 2][r] = b.z; Bs[kv + 3][r] = b.w;
        }
        __syncthreads();
        #pragma unroll
        for (int kk = 0; kk < 16; kk++) {
            float ra[8], rb[8];
            *(float4*)&ra[0] = *(const float4*)&As[kk][ty * 8];
            *(float4*)&ra[4] = *(const float4*)&As[kk][ty * 8 + 4];
            *(float4*)&rb[0] = *(const float4*)&Bs[kk][tx * 8];
            *(float4*)&rb[4] = *(const float4*)&Bs[kk][tx * 8 + 4];
            #pragma unroll
            for (int i = 0; i < 8; i++)
                #pragma unroll
                for (int j = 0; j < 8; j++)
                    acc[i][j] += ra[i] * rb[j];
        }
        __syncthreads();
    }

    #pragma unroll
    for (int i = 0; i < 8; i++) {
        int row = rowA0 + ty * 8 + i;
        #pragma unroll
        for (int j = 0; j < 8; j++) {
            int col = colB0 + tx * 8 + j;
            float v = acc[i][j] + bias[col];
            if (MODE == 0) {
                C[(size_t)row * N + col] = v;
            } else {
                int b = row >> 11, l = row & 2047;     // L = 2048
                int hh = col >> 6, hd = col & 63;      // HD = 64
                C[(((size_t)(b * HH + hh)) * LL + l) * HDIM + hd] = v;
            }
        }
    }
}

// ---------------- Flash attention (fp32, causal + key-padding) ----------------
// grid (32 q-tiles, B*H); 256 threads. Tiles 64x64. smem: Q,K,V,P @ 64x65 + mask.
#define TPAD 65
#define ATTN_SMEM (4 * 64 * TPAD * 4 + 64)

__global__ void attn_kernel() {
    extern __shared__ float smem[];
    float (*Qs)[TPAD] = (float(*)[TPAD])(smem);
    float (*Ks)[TPAD] = (float(*)[TPAD])(smem + 64 * TPAD);
    float (*Vs)[TPAD] = (float(*)[TPAD])(smem + 2 * 64 * TPAD);
    float (*Ps)[TPAD] = (float(*)[TPAD])(smem + 3 * 64 * TPAD);
    unsigned char* mk = (unsigned char*)(smem + 4 * 64 * TPAD);

    int qt = blockIdx.x;
    int bh = blockIdx.y;
    int b = bh / HH;
    int h = bh % HH;
    int tid = threadIdx.x;
    int ty = tid >> 4, tx = tid & 15;
    int qbase = qt * 64;

    const float* Qp = g_q + ((size_t)bh * LL + qbase) * HDIM;

    // load Q tile
    for (int i = tid; i < 1024; i += 256) {       // 1024 float4
        int r = i >> 4, c = (i & 15) * 4;
        float4 t = *(const float4*)&Qp[r * HDIM + c];
        Qs[r][c] = t.x; Qs[r][c + 1] = t.y; Qs[r][c + 2] = t.z; Qs[r][c + 3] = t.w;
    }

    float m_i[4], l_i[4], o[4][4];
    #pragma unroll
    for (int ri = 0; ri < 4; ri++) {
        m_i[ri] = -INFINITY; l_i[ri] = 0.f;
        #pragma unroll
        for (int ci = 0; ci < 4; ci++) o[ri][ci] = 0.f;
    }

    for (int j = 0; j <= qt; j++) {
        const float* Kp = g_k + ((size_t)bh * LL + j * 64) * HDIM;
        const float* Vp = g_v + ((size_t)bh * LL + j * 64) * HDIM;
        for (int i = tid; i < 1024; i += 256) {
            int r = i >> 4, c = (i & 15) * 4;
            float4 t = *(const float4*)&Kp[r * HDIM + c];
            Ks[r][c] = t.x; Ks[r][c + 1] = t.y; Ks[r][c + 2] = t.z; Ks[r][c + 3] = t.w;
            float4 u = *(const float4*)&Vp[r * HDIM + c];
            Vs[r][c] = u.x; Vs[r][c + 1] = u.y; Vs[r][c + 2] = u.z; Vs[r][c + 3] = u.w;
        }
        if (tid < 64) mk[tid] = g_mask[b * LL + j * 64 + tid];
        __syncthreads();

        // S = Q K^T (this thread: rows ty*4+ri, cols tx*4+ci)
        float s[4][4];
        #pragma unroll
        for (int ri = 0; ri < 4; ri++)
            #pragma unroll
            for (int ci = 0; ci < 4; ci++) s[ri][ci] = 0.f;
        for (int d = 0; d < 64; d++) {
            float qr[4], kr[4];
            #pragma unroll
            for (int ri = 0; ri < 4; ri++) qr[ri] = Qs[ty * 4 + ri][d];
            #pragma unroll
            for (int ci = 0; ci < 4; ci++) kr[ci] = Ks[tx * 4 + ci][d];
            #pragma unroll
            for (int ri = 0; ri < 4; ri++)
                #pragma unroll
                for (int ci = 0; ci < 4; ci++)
                    s[ri][ci] += qr[ri] * kr[ci];
        }

        // scale + causal + padding mask
        #pragma unroll
        for (int ri = 0; ri < 4; ri++) {
            int lg = qbase + ty * 4 + ri;
            #pragma unroll
            for (int ci = 0; ci < 4; ci++) {
                int kc = tx * 4 + ci;
                int kg = j * 64 + kc;
                float sv = s[ri][ci] * 0.125f;
                if (kg > lg || mk[kc]) sv = -1e30f;   // exp underflows to exactly 0
                s[ri][ci] = sv;
            }
        }

        // online softmax per row (reduce across the 16 lanes of each row group)
        #pragma unroll
        for (int ri = 0; ri < 4; ri++) {
            float mx = fmaxf(fmaxf(s[ri][0], s[ri][1]), fmaxf(s[ri][2], s[ri][3]));
            for (int off = 1; off < 16; off <<= 1)
                mx = fmaxf(mx, __shfl_xor_sync(0xffffffffu, mx, off));
            float mnew = fmaxf(m_i[ri], mx);
            float f = expf(m_i[ri] - mnew);           // exp(-inf)=0 on first tile
            float psum = 0.f;
            #pragma unroll
            for (int ci = 0; ci < 4; ci++) {
                float p = expf(s[ri][ci] - mnew);
                s[ri][ci] = p;
                psum += p;
            }
            for (int off = 1; off < 16; off <<= 1)
                psum += __shfl_xor_sync(0xffffffffu, psum, off);
            l_i[ri] = l_i[ri] * f + psum;
            m_i[ri] = mnew;
            #pragma unroll
            for (int ci = 0; ci < 4; ci++) {
                o[ri][ci] *= f;
                Ps[ty * 4 + ri][tx * 4 + ci] = s[ri][ci];
            }
        }
        __syncthreads();

        // O += P V
        for (int m = 0; m < 64; m++) {
            float pv[4], vv[4];
            #pragma unroll
            for (int ri = 0; ri < 4; ri++) pv[ri] = Ps[ty * 4 + ri][m];
            #pragma unroll
            for (int ci = 0; ci < 4; ci++) vv[ci] = Vs[m][tx * 4 + ci];
            #pragma unroll
            for (int ri = 0; ri < 4; ri++)
                #pragma unroll
                for (int ci = 0; ci < 4; ci++)
                    o[ri][ci] += pv[ri] * vv[ci];
        }
        __syncthreads();
    }

    // epilogue: normalize and write (B,L,D)
    #pragma unroll
    for (int ri = 0; ri < 4; ri++) {
        float inv = 1.0f / l_i[ri];
        int lg = qbase + ty * 4 + ri;
        #pragma unroll
        for (int ci = 0; ci < 4; ci++) {
            g_att[((size_t)b * LL + lg) * DD + h * HDIM + tx * 4 + ci] = o[ri][ci] * inv;
        }
    }
}

// ---------------- launch ----------------
extern "C" void kernel_launch(void* const* d_in, const int* in_sizes, int n_in,
                              void* d_out, int out_size) {
    const float* x  = (const float*)d_in[0];
    const unsigned char* pm = (const unsigned char*)d_in[1];
    // d_in[2] = causal_mask (unused; causality applied analytically)
    const float* Wq = (const float*)d_in[3];
    const float* bq = (const float*)d_in[4];
    const float* Wk = (const float*)d_in[5];
    const float* bk = (const float*)d_in[6];
    const float* Wv = (const float*)d_in[7];
    const float* bv = (const float*)d_in[8];
    const float* Wo = (const float*)d_in[9];
    const float* bo = (const float*)d_in[10];
    const float* g_pre = (const float*)d_in[11];
    const float* b_pre = (const float*)d_in[12];
    const float* g_ln  = (const float*)d_in[13];
    const float* b_ln  = (const float*)d_in[14];
    float* out = (float*)d_out;

    float *ph, *pq, *pk, *pv, *patt, *py;
    cudaGetSymbolAddress((void**)&ph,   g_h);
    cudaGetSymbolAddress((void**)&pq,   g_q);
    cudaGetSymbolAddress((void**)&pk,   g_k);
    cudaGetSymbolAddress((void**)&pv,   g_v);
    cudaGetSymbolAddress((void**)&patt, g_att);
    cudaGetSymbolAddress((void**)&py,   g_y);

    convert_mask_kernel<<<1, 256>>>(pm);

    // pre-LN
    ln_kernel<<<NROWS, 256>>>(x, (const float*)nullptr, g_pre, b_pre, ph);

    // QKV projections -> (B,H,L,HD)
    dim3 gproj(DD / 128, NROWS / 128);
    gemm_nt<1><<<gproj, 256>>>(ph, Wq, bq, pq, NROWS, DD, DD);
    gemm_nt<1><<<gproj, 256>>>(ph, Wk, bk, pk, NROWS, DD, DD);
    gemm_nt<1><<<gproj, 256>>>(ph, Wv, bv, pv, NROWS, DD, DD);

    // attention
    cudaFuncSetAttribute(attn_kernel, cudaFuncAttributeMaxDynamicSharedMemorySize, ATTN_SMEM);
    attn_kernel<<<dim3(LL / 64, BB * HH), 256, ATTN_SMEM>>>();

    // output projection
    gemm_nt<0><<<gproj, 256>>>(patt, Wo, bo, py, NROWS, DD, DD);

    // residual + final LN
    ln_kernel<<<NROWS, 256>>>(py, ph, g_ln, b_ln, out);
}

// round 3
// speedup vs baseline: 1.4661x; 1.4661x over previous
#include <cuda_runtime.h>
#include <cuda_bf16.h>
#include <math.h>
#include <stdint.h>

#define BB 4
#define LL 2048
#define DD 1024
#define HH 16
#define HDIM 64
#define NROWS (BB * LL)   // 8192

// ---------------- scratch (device globals; no allocation allowed) ----------------
__device__ float g_h[NROWS * DD];     // LN(x)
__device__ float g_q[NROWS * DD];     // (B,H,L,HD)
__device__ float g_k[NROWS * DD];
__device__ float g_v[NROWS * DD];
__device__ float g_att[NROWS * DD];   // attention out, (B,L,D)
__device__ float g_y[NROWS * DD];     // O-proj out
__device__ unsigned char g_mask[NROWS];
__device__ __nv_bfloat16 g_hHi[NROWS * DD];
__device__ __nv_bfloat16 g_hLo[NROWS * DD];
__device__ __nv_bfloat16 g_aHi[NROWS * DD];
__device__ __nv_bfloat16 g_aLo[NROWS * DD];
__device__ __nv_bfloat16 g_wHi[4][DD * DD];
__device__ __nv_bfloat16 g_wLo[4][DD * DD];

// ---------------- helpers ----------------
__device__ __forceinline__ uint32_t smem_u32(const void* p) {
    uint32_t a;
    asm("{ .reg .u64 t; cvta.to.shared.u64 t, %1; cvt.u32.u64 %0, t; }" : "=r"(a) : "l"(p));
    return a;
}
__device__ __forceinline__ void ldsm_x4(uint32_t& d0, uint32_t& d1, uint32_t& d2, uint32_t& d3,
                                        uint32_t addr) {
    asm volatile("ldmatrix.sync.aligned.m8n8.x4.shared.b16 {%0,%1,%2,%3}, [%4];"
                 : "=r"(d0), "=r"(d1), "=r"(d2), "=r"(d3) : "r"(addr));
}
__device__ __forceinline__ void mma16816(float* c, const uint32_t* a, const uint32_t* b) {
    asm volatile(
        "mma.sync.aligned.m16n8k16.row.col.f32.bf16.bf16.f32 "
        "{%0,%1,%2,%3}, {%4,%5,%6,%7}, {%8,%9}, {%0,%1,%2,%3};"
        : "+f"(c[0]), "+f"(c[1]), "+f"(c[2]), "+f"(c[3])
        : "r"(a[0]), "r"(a[1]), "r"(a[2]), "r"(a[3]), "r"(b[0]), "r"(b[1]));
}
#define CP_ASYNC16(dst, src) \
    asm volatile("cp.async.cg.shared.global [%0], [%1], 16;" :: "r"(dst), "l"(src))
#define CP_COMMIT() asm volatile("cp.async.commit_group;")
#define CP_WAIT1()  asm volatile("cp.async.wait_group 1;")
#define CP_WAIT0()  asm volatile("cp.async.wait_group 0;")

__device__ __forceinline__ uint32_t sw128(uint32_t off) {
    return off ^ ((off >> 3) & 0x70u);
}

// ---------------- padding-mask dtype detection + canonicalization ----------------
__global__ void convert_mask_kernel(const unsigned char* __restrict__ pm) {
    __shared__ int fz0, fz3;
    int tid = threadIdx.x;
    if (tid == 0) { fz0 = 0; fz3 = 0; }
    __syncthreads();
    int z0 = 0, z3 = 0;
    for (int j = tid; j < NROWS; j += blockDim.x) {
        unsigned char v = pm[j];
        if (v) {
            if ((j & 3) == 0) z0 = 1;
            if ((j & 3) == 3) z3 = 1;
        }
    }
    if (z0) atomicOr(&fz0, 1);
    if (z3) atomicOr(&fz3, 1);
    __syncthreads();
    int mode; // 0=all-zero, 1=uint8, 2=float32, 3=int32
    if (!fz3) mode = fz0 ? 3 : 0;
    else      mode = fz0 ? 1 : 2;
    for (int i = tid; i < NROWS; i += blockDim.x) {
        unsigned char r;
        if (mode == 0)      r = 0;
        else if (mode == 1) r = (pm[i] != 0);
        else if (mode == 2) r = (((const float*)pm)[i] != 0.0f);
        else                r = (((const int*)pm)[i] != 0);
        g_mask[i] = r;
    }
}

// ---------------- fp32 -> bf16 hi/lo split (exact two-term) ----------------
__global__ void split_kernel(const float* __restrict__ src,
                             __nv_bfloat16* __restrict__ hi,
                             __nv_bfloat16* __restrict__ lo, int n) {
    int i = (blockIdx.x * blockDim.x + threadIdx.x) * 4;
    if (i >= n) return;
    float4 v = *(const float4*)(src + i);
    __nv_bfloat162 h01, h23, l01, l23;
    float h;
    h = __bfloat162float(__float2bfloat16_rn(v.x)); h01.x = __float2bfloat16_rn(v.x); l01.x = __float2bfloat16_rn(v.x - h);
    h = __bfloat162float(__float2bfloat16_rn(v.y)); h01.y = __float2bfloat16_rn(v.y); l01.y = __float2bfloat16_rn(v.y - h);
    h = __bfloat162float(__float2bfloat16_rn(v.z)); h23.x = __float2bfloat16_rn(v.z); l23.x = __float2bfloat16_rn(v.z - h);
    h = __bfloat162float(__float2bfloat16_rn(v.w)); h23.y = __float2bfloat16_rn(v.w); l23.y = __float2bfloat16_rn(v.w - h);
    *(__nv_bfloat162*)(hi + i) = h01;
    *(__nv_bfloat162*)(hi + i + 2) = h23;
    *(__nv_bfloat162*)(lo + i) = l01;
    *(__nv_bfloat162*)(lo + i + 2) = l23;
}

// ---------------- LayerNorm (optionally fused residual add) ----------------
__global__ void ln_kernel(const float* __restrict__ x, const float* __restrict__ res,
                          const float* __restrict__ gamma, const float* __restrict__ beta,
                          float* __restrict__ out) {
    int row = blockIdx.x;
    int tid = threadIdx.x;
    const float4* xr = (const float4*)(x + (size_t)row * DD);
    float4 v = xr[tid];
    if (res) {
        const float4* rr = (const float4*)(res + (size_t)row * DD);
        float4 r2 = rr[tid];
        v.x += r2.x; v.y += r2.y; v.z += r2.z; v.w += r2.w;
    }
    float s  = v.x + v.y + v.z + v.w;
    float ss = v.x * v.x + v.y * v.y + v.z * v.z + v.w * v.w;
    for (int off = 16; off > 0; off >>= 1) {
        s  += __shfl_down_sync(0xffffffffu, s, off);
        ss += __shfl_down_sync(0xffffffffu, ss, off);
    }
    __shared__ float rs[8], rss[8];
    __shared__ float s_mu, s_rsig;
    int wid = tid >> 5, lane = tid & 31;
    if (lane == 0) { rs[wid] = s; rss[wid] = ss; }
    __syncthreads();
    if (tid == 0) {
        float S = 0.f, SS = 0.f;
        #pragma unroll
        for (int i = 0; i < 8; i++) { S += rs[i]; SS += rss[i]; }
        float mu  = S * (1.0f / DD);
        float var = SS * (1.0f / DD) - mu * mu;
        s_mu = mu;
        s_rsig = rsqrtf(var + 1e-5f);
    }
    __syncthreads();
    float mu = s_mu, rsig = s_rsig;
    float4 gv = ((const float4*)gamma)[tid];
    float4 bv = ((const float4*)beta)[tid];
    float4 o;
    o.x = (v.x - mu) * rsig * gv.x + bv.x;
    o.y = (v.y - mu) * rsig * gv.y + bv.y;
    o.z = (v.z - mu) * rsig * gv.z + bv.z;
    o.w = (v.w - mu) * rsig * gv.w + bv.w;
    ((float4*)(out + (size_t)row * DD))[tid] = o;
}

// ---------------- mma.sync split-bf16 GEMM ----------------
// C[i,j] = sum_k A[i,k]*W[j,k] + bias[j]; 3 split terms, K_eff = 3072.
// 128x128 C tile per CTA, BK=64 chunks, double-buffered cp.async, SW128 smem.
// 8 warps: warp_m = wid&3 (32 rows), warp_n = wid>>2 (64 cols).
// MODE 0: row-major [8192,1024].  MODE 1: scatter to (B,H,L,HD).
#define GSMEM (64 * 1024)

template <int MODE>
__global__ __launch_bounds__(256, 2)
void gemm_mma(const __nv_bfloat16* __restrict__ Ahi, const __nv_bfloat16* __restrict__ Alo,
              const __nv_bfloat16* __restrict__ Bhi, const __nv_bfloat16* __restrict__ Blo,
              const float* __restrict__ bias, float* __restrict__ C) {
    extern __shared__ char dsm[];
    __shared__ float s_bias[128];

    int tid = threadIdx.x;
    int wid = tid >> 5;
    int lane = tid & 31;
    int warp_m = wid & 3;
    int warp_n = wid >> 2;
    int rowA0 = blockIdx.y * 128;
    int colB0 = blockIdx.x * 128;

    uint32_t base = smem_u32(dsm);
    // layout: A0 @0, B0 @16K, A1 @32K, B1 @48K
    uint32_t aBase[2] = { base, base + 32768u };
    uint32_t bBase[2] = { base + 16384u, base + 49152u };

    if (tid < 128) s_bias[tid] = bias[colB0 + tid];

    const __nv_bfloat16* TA[3] = { Ahi, Ahi, Alo };
    const __nv_bfloat16* TB[3] = { Bhi, Blo, Bhi };

    // per-thread load mapping: 4 chunks of 16B per array per stage
    int ldR[4], ldC[4];
    uint32_t ldSw[4];
    #pragma unroll
    for (int it = 0; it < 4; it++) {
        int lin = it * 256 + tid;       // 0..1023
        ldR[it] = lin >> 3;             // row 0..127
        ldC[it] = (lin & 7) * 8;        // k element 0..56
        ldSw[it] = sw128((uint32_t)(ldR[it] * 128 + (lin & 7) * 16));
    }

    auto issue = [&](int i, int s) {
        int term = i >> 4;
        int k0 = (i & 15) * 64;
        const __nv_bfloat16* Ag = TA[term];
        const __nv_bfloat16* Bg = TB[term];
        #pragma unroll
        for (int it = 0; it < 4; it++) {
            const __nv_bfloat16* ga = Ag + (size_t)(rowA0 + ldR[it]) * DD + k0 + ldC[it];
            CP_ASYNC16(aBase[s] + ldSw[it], ga);
            const __nv_bfloat16* gb = Bg + (size_t)(colB0 + ldR[it]) * DD + k0 + ldC[it];
            CP_ASYNC16(bBase[s] + ldSw[it], gb);
        }
        CP_COMMIT();
    };

    float acc[2][8][4];
    #pragma unroll
    for (int mt = 0; mt < 2; mt++)
        #pragma unroll
        for (int nt = 0; nt < 8; nt++)
            #pragma unroll
            for (int q = 0; q < 4; q++) acc[mt][nt][q] = 0.f;

    // precompute per-lane ldmatrix row/chunk components
    int aRow = warp_m * 32 + (lane & 15);        // + mt*16
    int aChunkHalf = lane >> 4;                  // + ks*2
    int bRow = warp_n * 64 + (lane >> 4) * 8 + (lane & 7);  // + j2*16
    int bChunkHalf = (lane >> 3) & 1;            // + ks*2

    issue(0, 0);

    for (int i = 0; i < 48; i++) {
        int s = i & 1;
        if (i < 47) issue(i + 1, s ^ 1);
        if (i < 47) { CP_WAIT1(); } else { CP_WAIT0(); }
        __syncthreads();

        #pragma unroll
        for (int ks = 0; ks < 4; ks++) {
            uint32_t af[2][4];
            #pragma unroll
            for (int mt = 0; mt < 2; mt++) {
                uint32_t off = (uint32_t)((aRow + mt * 16) * 128 + (ks * 2 + aChunkHalf) * 16);
                ldsm_x4(af[mt][0], af[mt][1], af[mt][2], af[mt][3], aBase[s] + sw128(off));
            }
            uint32_t bf[8][2];
            #pragma unroll
            for (int j2 = 0; j2 < 4; j2++) {
                uint32_t off = (uint32_t)((bRow + j2 * 16) * 128 + (ks * 2 + bChunkHalf) * 16);
                uint32_t r0, r1, r2, r3;
                ldsm_x4(r0, r1, r2, r3, bBase[s] + sw128(off));
                bf[j2 * 2][0] = r0; bf[j2 * 2][1] = r1;
                bf[j2 * 2 + 1][0] = r2; bf[j2 * 2 + 1][1] = r3;
            }
            #pragma unroll
            for (int mt = 0; mt < 2; mt++)
                #pragma unroll
                for (int nt = 0; nt < 8; nt++)
                    mma16816(acc[mt][nt], af[mt], bf[nt]);
        }
        __syncthreads();
    }

    // epilogue
    int gid = lane >> 2, tig = lane & 3;
    #pragma unroll
    for (int mt = 0; mt < 2; mt++) {
        #pragma unroll
        for (int half = 0; half < 2; half++) {
            int m = rowA0 + warp_m * 32 + mt * 16 + gid + half * 8;
            #pragma unroll
            for (int nt = 0; nt < 8; nt++) {
                int col = colB0 + warp_n * 64 + nt * 8 + tig * 2;
                float2 v;
                v.x = acc[mt][nt][half * 2 + 0] + s_bias[col - colB0];
                v.y = acc[mt][nt][half * 2 + 1] + s_bias[col - colB0 + 1];
                if (MODE == 0) {
                    *(float2*)(C + (size_t)m * DD + col) = v;
                } else {
                    int b = m >> 11, l = m & 2047;
                    int hh = col >> 6, hd = col & 63;
                    *(float2*)(C + (((size_t)(b * HH + hh)) * LL + l) * HDIM + hd) = v;
                }
            }
        }
    }
}

// ---------------- Flash attention (fp32, causal + key-padding) ----------------
#define TPAD 65
#define ATTN_SMEM (4 * 64 * TPAD * 4 + 64)

__global__ void attn_kernel() {
    extern __shared__ float smem[];
    float (*Qs)[TPAD] = (float(*)[TPAD])(smem);
    float (*Ks)[TPAD] = (float(*)[TPAD])(smem + 64 * TPAD);
    float (*Vs)[TPAD] = (float(*)[TPAD])(smem + 2 * 64 * TPAD);
    float (*Ps)[TPAD] = (float(*)[TPAD])(smem + 3 * 64 * TPAD);
    unsigned char* mk = (unsigned char*)(smem + 4 * 64 * TPAD);

    int qt = blockIdx.x;
    int bh = blockIdx.y;
    int b = bh / HH;
    int h = bh % HH;
    int tid = threadIdx.x;
    int ty = tid >> 4, tx = tid & 15;
    int qbase = qt * 64;

    const float* Qp = g_q + ((size_t)bh * LL + qbase) * HDIM;

    for (int i = tid; i < 1024; i += 256) {
        int r = i >> 4, c = (i & 15) * 4;
        float4 t = *(const float4*)&Qp[r * HDIM + c];
        Qs[r][c] = t.x; Qs[r][c + 1] = t.y; Qs[r][c + 2] = t.z; Qs[r][c + 3] = t.w;
    }

    float m_i[4], l_i[4], o[4][4];
    #pragma unroll
    for (int ri = 0; ri < 4; ri++) {
        m_i[ri] = -INFINITY; l_i[ri] = 0.f;
        #pragma unroll
        for (int ci = 0; ci < 4; ci++) o[ri][ci] = 0.f;
    }

    for (int j = 0; j <= qt; j++) {
        const float* Kp = g_k + ((size_t)bh * LL + j * 64) * HDIM;
        const float* Vp = g_v + ((size_t)bh * LL + j * 64) * HDIM;
        for (int i = tid; i < 1024; i += 256) {
            int r = i >> 4, c = (i & 15) * 4;
            float4 t = *(const float4*)&Kp[r * HDIM + c];
            Ks[r][c] = t.x; Ks[r][c + 1] = t.y; Ks[r][c + 2] = t.z; Ks[r][c + 3] = t.w;
            float4 u = *(const float4*)&Vp[r * HDIM + c];
            Vs[r][c] = u.x; Vs[r][c + 1] = u.y; Vs[r][c + 2] = u.z; Vs[r][c + 3] = u.w;
        }
        if (tid < 64) mk[tid] = g_mask[b * LL + j * 64 + tid];
        __syncthreads();

        float s[4][4];
        #pragma unroll
        for (int ri = 0; ri < 4; ri++)
            #pragma unroll
            for (int ci = 0; ci < 4; ci++) s[ri][ci] = 0.f;
        for (int d = 0; d < 64; d++) {
            float qr[4], kr[4];
            #pragma unroll
            for (int ri = 0; ri < 4; ri++) qr[ri] = Qs[ty * 4 + ri][d];
            #pragma unroll
            for (int ci = 0; ci < 4; ci++) kr[ci] = Ks[tx * 4 + ci][d];
            #pragma unroll
            for (int ri = 0; ri < 4; ri++)
                #pragma unroll
                for (int ci = 0; ci < 4; ci++)
                    s[ri][ci] += qr[ri] * kr[ci];
        }

        #pragma unroll
        for (int ri = 0; ri < 4; ri++) {
            int lg = qbase + ty * 4 + ri;
            #pragma unroll
            for (int ci = 0; ci < 4; ci++) {
                int kc = tx * 4 + ci;
                int kg = j * 64 + kc;
                float sv = s[ri][ci] * 0.125f;
                if (kg > lg || mk[kc]) sv = -1e30f;
                s[ri][ci] = sv;
            }
        }

        #pragma unroll
        for (int ri = 0; ri < 4; ri++) {
            float mx = fmaxf(fmaxf(s[ri][0], s[ri][1]), fmaxf(s[ri][2], s[ri][3]));
            for (int off = 1; off < 16; off <<= 1)
                mx = fmaxf(mx, __shfl_xor_sync(0xffffffffu, mx, off));
            float mnew = fmaxf(m_i[ri], mx);
            float f = expf(m_i[ri] - mnew);
            float psum = 0.f;
            #pragma unroll
            for (int ci = 0; ci < 4; ci++) {
                float p = expf(s[ri][ci] - mnew);
                s[ri][ci] = p;
                psum += p;
            }
            for (int off = 1; off < 16; off <<= 1)
                psum += __shfl_xor_sync(0xffffffffu, psum, off);
            l_i[ri] = l_i[ri] * f + psum;
            m_i[ri] = mnew;
            #pragma unroll
            for (int ci = 0; ci < 4; ci++) {
                o[ri][ci] *= f;
                Ps[ty * 4 + ri][tx * 4 + ci] = s[ri][ci];
            }
        }
        __syncthreads();

        for (int m = 0; m < 64; m++) {
            float pv[4], vv[4];
            #pragma unroll
            for (int ri = 0; ri < 4; ri++) pv[ri] = Ps[ty * 4 + ri][m];
            #pragma unroll
            for (int ci = 0; ci < 4; ci++) vv[ci] = Vs[m][tx * 4 + ci];
            #pragma unroll
            for (int ri = 0; ri < 4; ri++)
                #pragma unroll
                for (int ci = 0; ci < 4; ci++)
                    o[ri][ci] += pv[ri] * vv[ci];
        }
        __syncthreads();
    }

    #pragma unroll
    for (int ri = 0; ri < 4; ri++) {
        float inv = 1.0f / l_i[ri];
        int lg = qbase + ty * 4 + ri;
        #pragma unroll
        for (int ci = 0; ci < 4; ci++) {
            g_att[((size_t)b * LL + lg) * DD + h * HDIM + tx * 4 + ci] = o[ri][ci] * inv;
        }
    }
}

// ---------------- launch ----------------
extern "C" void kernel_launch(void* const* d_in, const int* in_sizes, int n_in,
                              void* d_out, int out_size) {
    const float* x  = (const float*)d_in[0];
    const unsigned char* pm = (const unsigned char*)d_in[1];
    const float* Wq = (const float*)d_in[3];
    const float* bq = (const float*)d_in[4];
    const float* Wk = (const float*)d_in[5];
    const float* bk = (const float*)d_in[6];
    const float* Wv = (const float*)d_in[7];
    const float* bv = (const float*)d_in[8];
    const float* Wo = (const float*)d_in[9];
    const float* bo = (const float*)d_in[10];
    const float* g_pre = (const float*)d_in[11];
    const float* b_pre = (const float*)d_in[12];
    const float* g_ln  = (const float*)d_in[13];
    const float* b_ln  = (const float*)d_in[14];
    float* out = (float*)d_out;

    float *ph, *pq, *pk, *pv, *patt, *py;
    __nv_bfloat16 *phHi, *phLo, *paHi, *paLo, *pwHi, *pwLo;
    cudaGetSymbolAddress((void**)&ph,   g_h);
    cudaGetSymbolAddress((void**)&pq,   g_q);
    cudaGetSymbolAddress((void**)&pk,   g_k);
    cudaGetSymbolAddress((void**)&pv,   g_v);
    cudaGetSymbolAddress((void**)&patt, g_att);
    cudaGetSymbolAddress((void**)&py,   g_y);
    cudaGetSymbolAddress((void**)&phHi, g_hHi);
    cudaGetSymbolAddress((void**)&phLo, g_hLo);
    cudaGetSymbolAddress((void**)&paHi, g_aHi);
    cudaGetSymbolAddress((void**)&paLo, g_aLo);
    cudaGetSymbolAddress((void**)&pwHi, g_wHi);
    cudaGetSymbolAddress((void**)&pwLo, g_wLo);

    cudaFuncSetAttribute(gemm_mma<0>, cudaFuncAttributeMaxDynamicSharedMemorySize, GSMEM);
    cudaFuncSetAttribute(gemm_mma<1>, cudaFuncAttributeMaxDynamicSharedMemorySize, GSMEM);
    cudaFuncSetAttribute(attn_kernel, cudaFuncAttributeMaxDynamicSharedMemorySize, ATTN_SMEM);

    convert_mask_kernel<<<1, 256>>>(pm);

    // pre-LN
    ln_kernel<<<NROWS, 256>>>(x, (const float*)nullptr, g_pre, b_pre, ph);

    // splits: activations + weights
    const int nAct = NROWS * DD;          // 8388608
    const int nW   = DD * DD;             // 1048576
    split_kernel<<<nAct / 1024, 256>>>(ph, phHi, phLo, nAct);
    split_kernel<<<nW / 1024, 256>>>(Wq, pwHi + 0 * (size_t)nW, pwLo + 0 * (size_t)nW, nW);
    split_kernel<<<nW / 1024, 256>>>(Wk, pwHi + 1 * (size_t)nW, pwLo + 1 * (size_t)nW, nW);
    split_kernel<<<nW / 1024, 256>>>(Wv, pwHi + 2 * (size_t)nW, pwLo + 2 * (size_t)nW, nW);
    split_kernel<<<nW / 1024, 256>>>(Wo, pwHi + 3 * (size_t)nW, pwLo + 3 * (size_t)nW, nW);

    // QKV projections -> (B,H,L,HD) via mma.sync
    dim3 gproj(DD / 128, NROWS / 128);
    gemm_mma<1><<<gproj, 256, GSMEM>>>(phHi, phLo, pwHi + 0 * (size_t)nW, pwLo + 0 * (size_t)nW, bq, pq);
    gemm_mma<1><<<gproj, 256, GSMEM>>>(phHi, phLo, pwHi + 1 * (size_t)nW, pwLo + 1 * (size_t)nW, bk, pk);
    gemm_mma<1><<<gproj, 256, GSMEM>>>(phHi, phLo, pwHi + 2 * (size_t)nW, pwLo + 2 * (size_t)nW, bv, pv);

    // attention
    attn_kernel<<<dim3(LL / 64, BB * HH), 256, ATTN_SMEM>>>();

    // output projection
    split_kernel<<<nAct / 1024, 256>>>(patt, paHi, paLo, nAct);
    gemm_mma<0><<<gproj, 256, GSMEM>>>(paHi, paLo, pwHi + 3 * (size_t)nW, pwLo + 3 * (size_t)nW, bo, py);

    // residual + final LN
    ln_kernel<<<NROWS, 256>>>(py, ph, g_ln, b_ln, out);
}

// round 4
// speedup vs baseline: 3.0457x; 2.0775x over previous
#include <cuda_runtime.h>
#include <cuda_bf16.h>
#include <math.h>
#include <stdint.h>

#define BB 4
#define LL 2048
#define DD 1024
#define HH 16
#define HDIM 64
#define NROWS (BB * LL)   // 8192

// ---------------- scratch ----------------
__device__ float g_h[NROWS * DD];     // LN(x)
__device__ float g_att[NROWS * DD];   // attention out, (B,L,D)
__device__ float g_y[NROWS * DD];     // O-proj out
__device__ unsigned char g_mask[NROWS];
__device__ __nv_bfloat16 g_hHi[NROWS * DD];
__device__ __nv_bfloat16 g_hLo[NROWS * DD];
__device__ __nv_bfloat16 g_aHi[NROWS * DD];
__device__ __nv_bfloat16 g_aLo[NROWS * DD];
__device__ __nv_bfloat16 g_wHi[4][DD * DD];
__device__ __nv_bfloat16 g_wLo[4][DD * DD];
__device__ __nv_bfloat16 g_qHi[NROWS * DD];   // (B,H,L,HD)
__device__ __nv_bfloat16 g_qLo[NROWS * DD];
__device__ __nv_bfloat16 g_kHi[NROWS * DD];
__device__ __nv_bfloat16 g_kLo[NROWS * DD];
__device__ __nv_bfloat16 g_vHi[NROWS * DD];
__device__ __nv_bfloat16 g_vLo[NROWS * DD];

// ---------------- helpers ----------------
__device__ __forceinline__ uint32_t smem_u32(const void* p) {
    uint32_t a;
    asm("{ .reg .u64 t; cvta.to.shared.u64 t, %1; cvt.u32.u64 %0, t; }" : "=r"(a) : "l"(p));
    return a;
}
__device__ __forceinline__ void ldsm_x4(uint32_t& d0, uint32_t& d1, uint32_t& d2, uint32_t& d3,
                                        uint32_t addr) {
    asm volatile("ldmatrix.sync.aligned.m8n8.x4.shared.b16 {%0,%1,%2,%3}, [%4];"
                 : "=r"(d0), "=r"(d1), "=r"(d2), "=r"(d3) : "r"(addr));
}
__device__ __forceinline__ void ldsm_x4t(uint32_t& d0, uint32_t& d1, uint32_t& d2, uint32_t& d3,
                                         uint32_t addr) {
    asm volatile("ldmatrix.sync.aligned.m8n8.x4.trans.shared.b16 {%0,%1,%2,%3}, [%4];"
                 : "=r"(d0), "=r"(d1), "=r"(d2), "=r"(d3) : "r"(addr));
}
__device__ __forceinline__ void mma16816(float* c, const uint32_t* a, const uint32_t* b) {
    asm volatile(
        "mma.sync.aligned.m16n8k16.row.col.f32.bf16.bf16.f32 "
        "{%0,%1,%2,%3}, {%4,%5,%6,%7}, {%8,%9}, {%0,%1,%2,%3};"
        : "+f"(c[0]), "+f"(c[1]), "+f"(c[2]), "+f"(c[3])
        : "r"(a[0]), "r"(a[1]), "r"(a[2]), "r"(a[3]), "r"(b[0]), "r"(b[1]));
}
#define CP_ASYNC16(dst, src) \
    asm volatile("cp.async.cg.shared.global [%0], [%1], 16;" :: "r"(dst), "l"(src))
#define CP_COMMIT() asm volatile("cp.async.commit_group;")
#define CP_WAIT1()  asm volatile("cp.async.wait_group 1;")
#define CP_WAIT0()  asm volatile("cp.async.wait_group 0;")

__device__ __forceinline__ uint32_t sw128(uint32_t off) {
    return off ^ ((off >> 3) & 0x70u);
}
__device__ __forceinline__ void split2(float a, float b, uint32_t& hi, uint32_t& lo) {
    __nv_bfloat16 ha = __float2bfloat16_rn(a), hb = __float2bfloat16_rn(b);
    float ra = a - __bfloat162float(ha), rb = b - __bfloat162float(hb);
    __nv_bfloat162 h2; h2.x = ha; h2.y = hb;
    __nv_bfloat162 l2; l2.x = __float2bfloat16_rn(ra); l2.y = __float2bfloat16_rn(rb);
    hi = *(uint32_t*)&h2;
    lo = *(uint32_t*)&l2;
}

// ---------------- padding-mask canonicalization ----------------
__global__ void convert_mask_kernel(const unsigned char* __restrict__ pm) {
    __shared__ int fz0, fz3;
    int tid = threadIdx.x;
    if (tid == 0) { fz0 = 0; fz3 = 0; }
    __syncthreads();
    int z0 = 0, z3 = 0;
    for (int j = tid; j < NROWS; j += blockDim.x) {
        unsigned char v = pm[j];
        if (v) {
            if ((j & 3) == 0) z0 = 1;
            if ((j & 3) == 3) z3 = 1;
        }
    }
    if (z0) atomicOr(&fz0, 1);
    if (z3) atomicOr(&fz3, 1);
    __syncthreads();
    int mode;
    if (!fz3) mode = fz0 ? 3 : 0;
    else      mode = fz0 ? 1 : 2;
    for (int i = tid; i < NROWS; i += blockDim.x) {
        unsigned char r;
        if (mode == 0)      r = 0;
        else if (mode == 1) r = (pm[i] != 0);
        else if (mode == 2) r = (((const float*)pm)[i] != 0.0f);
        else                r = (((const int*)pm)[i] != 0);
        g_mask[i] = r;
    }
}

// ---------------- fp32 -> bf16 hi/lo split ----------------
__global__ void split_kernel(const float* __restrict__ src,
                             __nv_bfloat16* __restrict__ hi,
                             __nv_bfloat16* __restrict__ lo, int n) {
    int i = (blockIdx.x * blockDim.x + threadIdx.x) * 4;
    if (i >= n) return;
    float4 v = *(const float4*)(src + i);
    uint32_t h01, l01, h23, l23;
    split2(v.x, v.y, h01, l01);
    split2(v.z, v.w, h23, l23);
    *(uint32_t*)(hi + i) = h01; *(uint32_t*)(hi + i + 2) = h23;
    *(uint32_t*)(lo + i) = l01; *(uint32_t*)(lo + i + 2) = l23;
}

// ---------------- LayerNorm ----------------
__global__ void ln_kernel(const float* __restrict__ x, const float* __restrict__ res,
                          const float* __restrict__ gamma, const float* __restrict__ beta,
                          float* __restrict__ out) {
    int row = blockIdx.x;
    int tid = threadIdx.x;
    const float4* xr = (const float4*)(x + (size_t)row * DD);
    float4 v = xr[tid];
    if (res) {
        const float4* rr = (const float4*)(res + (size_t)row * DD);
        float4 r2 = rr[tid];
        v.x += r2.x; v.y += r2.y; v.z += r2.z; v.w += r2.w;
    }
    float s  = v.x + v.y + v.z + v.w;
    float ss = v.x * v.x + v.y * v.y + v.z * v.z + v.w * v.w;
    for (int off = 16; off > 0; off >>= 1) {
        s  += __shfl_down_sync(0xffffffffu, s, off);
        ss += __shfl_down_sync(0xffffffffu, ss, off);
    }
    __shared__ float rs[8], rss[8];
    __shared__ float s_mu, s_rsig;
    int wid = tid >> 5, lane = tid & 31;
    if (lane == 0) { rs[wid] = s; rss[wid] = ss; }
    __syncthreads();
    if (tid == 0) {
        float S = 0.f, SS = 0.f;
        #pragma unroll
        for (int i = 0; i < 8; i++) { S += rs[i]; SS += rss[i]; }
        float mu  = S * (1.0f / DD);
        float var = SS * (1.0f / DD) - mu * mu;
        s_mu = mu;
        s_rsig = rsqrtf(var + 1e-5f);
    }
    __syncthreads();
    float mu = s_mu, rsig = s_rsig;
    float4 gv = ((const float4*)gamma)[tid];
    float4 bv = ((const float4*)beta)[tid];
    float4 o;
    o.x = (v.x - mu) * rsig * gv.x + bv.x;
    o.y = (v.y - mu) * rsig * gv.y + bv.y;
    o.z = (v.z - mu) * rsig * gv.z + bv.z;
    o.w = (v.w - mu) * rsig * gv.w + bv.w;
    ((float4*)(out + (size_t)row * DD))[tid] = o;
}

// ---------------- mma.sync split-bf16 GEMM ----------------
// MODE 0: C row-major fp32.  MODE 1: bf16 hi/lo scatter to (B,H,L,HD).
#define GSMEM (64 * 1024)

template <int MODE>
__global__ __launch_bounds__(256, 2)
void gemm_mma(const __nv_bfloat16* __restrict__ Ahi, const __nv_bfloat16* __restrict__ Alo,
              const __nv_bfloat16* __restrict__ Bhi, const __nv_bfloat16* __restrict__ Blo,
              const float* __restrict__ bias, float* __restrict__ C,
              __nv_bfloat16* __restrict__ CHi, __nv_bfloat16* __restrict__ CLo) {
    extern __shared__ char dsm[];
    __shared__ float s_bias[128];

    int tid = threadIdx.x;
    int wid = tid >> 5;
    int lane = tid & 31;
    int warp_m = wid & 3;
    int warp_n = wid >> 2;
    int rowA0 = blockIdx.y * 128;
    int colB0 = blockIdx.x * 128;

    uint32_t base = smem_u32(dsm);
    uint32_t aBase[2] = { base, base + 32768u };
    uint32_t bBase[2] = { base + 16384u, base + 49152u };

    if (tid < 128) s_bias[tid] = bias[colB0 + tid];

    const __nv_bfloat16* TA[3] = { Ahi, Ahi, Alo };
    const __nv_bfloat16* TB[3] = { Bhi, Blo, Bhi };

    int ldR[4], ldC[4];
    uint32_t ldSw[4];
    #pragma unroll
    for (int it = 0; it < 4; it++) {
        int lin = it * 256 + tid;
        ldR[it] = lin >> 3;
        ldC[it] = (lin & 7) * 8;
        ldSw[it] = sw128((uint32_t)(ldR[it] * 128 + (lin & 7) * 16));
    }

    auto issue = [&](int i, int s) {
        int term = i >> 4;
        int k0 = (i & 15) * 64;
        const __nv_bfloat16* Ag = TA[term];
        const __nv_bfloat16* Bg = TB[term];
        #pragma unroll
        for (int it = 0; it < 4; it++) {
            CP_ASYNC16(aBase[s] + ldSw[it], Ag + (size_t)(rowA0 + ldR[it]) * DD + k0 + ldC[it]);
            CP_ASYNC16(bBase[s] + ldSw[it], Bg + (size_t)(colB0 + ldR[it]) * DD + k0 + ldC[it]);
        }
        CP_COMMIT();
    };

    float acc[2][8][4];
    #pragma unroll
    for (int mt = 0; mt < 2; mt++)
        #pragma unroll
        for (int nt = 0; nt < 8; nt++)
            #pragma unroll
            for (int q = 0; q < 4; q++) acc[mt][nt][q] = 0.f;

    int aRow = warp_m * 32 + (lane & 15);
    int aChunkHalf = lane >> 4;
    int bRow = warp_n * 64 + (lane >> 4) * 8 + (lane & 7);
    int bChunkHalf = (lane >> 3) & 1;

    issue(0, 0);

    for (int i = 0; i < 48; i++) {
        int s = i & 1;
        if (i < 47) issue(i + 1, s ^ 1);
        if (i < 47) { CP_WAIT1(); } else { CP_WAIT0(); }
        __syncthreads();

        #pragma unroll
        for (int ks = 0; ks < 4; ks++) {
            uint32_t af[2][4];
            #pragma unroll
            for (int mt = 0; mt < 2; mt++) {
                uint32_t off = (uint32_t)((aRow + mt * 16) * 128 + (ks * 2 + aChunkHalf) * 16);
                ldsm_x4(af[mt][0], af[mt][1], af[mt][2], af[mt][3], aBase[s] + sw128(off));
            }
            uint32_t bf[8][2];
            #pragma unroll
            for (int j2 = 0; j2 < 4; j2++) {
                uint32_t off = (uint32_t)((bRow + j2 * 16) * 128 + (ks * 2 + bChunkHalf) * 16);
                uint32_t r0, r1, r2, r3;
                ldsm_x4(r0, r1, r2, r3, bBase[s] + sw128(off));
                bf[j2 * 2][0] = r0; bf[j2 * 2][1] = r1;
                bf[j2 * 2 + 1][0] = r2; bf[j2 * 2 + 1][1] = r3;
            }
            #pragma unroll
            for (int mt = 0; mt < 2; mt++)
                #pragma unroll
                for (int nt = 0; nt < 8; nt++)
                    mma16816(acc[mt][nt], af[mt], bf[nt]);
        }
        __syncthreads();
    }

    int gid = lane >> 2, tig = lane & 3;
    #pragma unroll
    for (int mt = 0; mt < 2; mt++) {
        #pragma unroll
        for (int half = 0; half < 2; half++) {
            int m = rowA0 + warp_m * 32 + mt * 16 + gid + half * 8;
            #pragma unroll
            for (int nt = 0; nt < 8; nt++) {
                int col = colB0 + warp_n * 64 + nt * 8 + tig * 2;
                float vx = acc[mt][nt][half * 2 + 0] + s_bias[col - colB0];
                float vy = acc[mt][nt][half * 2 + 1] + s_bias[col - colB0 + 1];
                if (MODE == 0) {
                    float2 v; v.x = vx; v.y = vy;
                    *(float2*)(C + (size_t)m * DD + col) = v;
                } else {
                    int b = m >> 11, l = m & 2047;
                    int hh = col >> 6, hd = col & 63;
                    size_t idx = (((size_t)(b * HH + hh)) * LL + l) * HDIM + hd;
                    uint32_t hi2, lo2;
                    split2(vx, vy, hi2, lo2);
                    *(uint32_t*)(CHi + idx) = hi2;
                    *(uint32_t*)(CLo + idx) = lo2;
                }
            }
        }
    }
}

// ---------------- tensor-core flash attention ----------------
// CTA: 128 q-rows, one (b,h). 8 warps x 16 rows. K/V tiles 64 keys, double-buffered.
#define ASMEM (64 * 1024)

__global__ __launch_bounds__(256, 1)
void attn_mma() {
    extern __shared__ char dsm[];
    __shared__ unsigned char s_mk[2][64];

    int tid = threadIdx.x;
    int wid = tid >> 5;
    int lane = tid & 31;
    int gid = lane >> 2, tig = lane & 3;
    int qt = blockIdx.x;
    int bh = blockIdx.y;
    int b = bh >> 4, h = bh & 15;
    int qbase = qt * 128;

    uint32_t base = smem_u32(dsm);
    // stage s: Khi @ s*32768, Klo +8192, Vhi +16384, Vlo +24576

    const __nv_bfloat16* qHi = g_qHi + ((size_t)bh * LL + qbase) * HDIM;
    const __nv_bfloat16* qLo = g_qLo + ((size_t)bh * LL + qbase) * HDIM;

    // ---- stage Q (hi @ base, lo @ base+16384), extract to registers ----
    #pragma unroll
    for (int it = 0; it < 4; it++) {
        int c = it * 256 + tid;
        int row = c >> 3, col16 = c & 7;
        uint32_t sw = sw128((uint32_t)(row * 128 + col16 * 16));
        CP_ASYNC16(base + sw, qHi + row * HDIM + col16 * 8);
        CP_ASYNC16(base + 16384u + sw, qLo + row * HDIM + col16 * 8);
    }
    CP_COMMIT();
    CP_WAIT0();
    __syncthreads();

    uint32_t qh[4][4], ql[4][4];
    {
        int arow = wid * 16 + (lane & 15);
        int ahalf = lane >> 4;
        #pragma unroll
        for (int ks = 0; ks < 4; ks++) {
            uint32_t off = (uint32_t)(arow * 128 + (ks * 2 + ahalf) * 16);
            ldsm_x4(qh[ks][0], qh[ks][1], qh[ks][2], qh[ks][3], base + sw128(off));
            ldsm_x4(ql[ks][0], ql[ks][1], ql[ks][2], ql[ks][3], base + 16384u + sw128(off));
        }
    }
    __syncthreads();

    int ntiles = 2 * qt + 2;

    auto issue = [&](int j, int s) {
        uint32_t st = base + (uint32_t)s * 32768u;
        size_t goff = ((size_t)bh * LL + j * 64) * HDIM;
        #pragma unroll
        for (int it = 0; it < 2; it++) {
            int c = it * 256 + tid;
            int row = c >> 3, col16 = c & 7;
            uint32_t sw = sw128((uint32_t)(row * 128 + col16 * 16));
            size_t so = goff + row * HDIM + col16 * 8;
            CP_ASYNC16(st + sw,          g_kHi + so);
            CP_ASYNC16(st + 8192u + sw,  g_kLo + so);
            CP_ASYNC16(st + 16384u + sw, g_vHi + so);
            CP_ASYNC16(st + 24576u + sw, g_vLo + so);
        }
        if (tid < 64) s_mk[s][tid] = g_mask[b * LL + j * 64 + tid];
        CP_COMMIT();
    };

    float o[8][4];
    #pragma unroll
    for (int nt = 0; nt < 8; nt++)
        #pragma unroll
        for (int q = 0; q < 4; q++) o[nt][q] = 0.f;
    float m0 = -1e30f, m1 = -1e30f, l0 = 0.f, l1 = 0.f;

    const float cs = 0.125f * 1.4426950408889634f;  // 1/sqrt(HD) * log2(e)
    int qg0 = qbase + wid * 16 + gid;
    int qg1 = qg0 + 8;

    issue(0, 0);
    int issued = 1;
    if (ntiles > 1) { issue(1, 1); issued = 2; }

    int kRow = (lane >> 4) * 8 + (lane & 7);
    int kHalf = (lane >> 3) & 1;
    int vRowL = lane & 15;
    int vHalf = lane >> 4;

    for (int j = 0; j < ntiles; j++) {
        int s = j & 1;
        if (issued > j + 1) { CP_WAIT1(); } else { CP_WAIT0(); }
        __syncthreads();

        uint32_t stK = base + (uint32_t)s * 32768u;
        uint32_t stV = stK + 16384u;

        // ---- S = Q K^T (3-term split) ----
        float sa[8][4];
        #pragma unroll
        for (int nt = 0; nt < 8; nt++)
            #pragma unroll
            for (int q = 0; q < 4; q++) sa[nt][q] = 0.f;

        #pragma unroll
        for (int ks = 0; ks < 4; ks++) {
            uint32_t bh_[8][2], bl_[8][2];
            #pragma unroll
            for (int j2 = 0; j2 < 4; j2++) {
                uint32_t off = (uint32_t)((kRow + j2 * 16) * 128 + (ks * 2 + kHalf) * 16);
                uint32_t r0, r1, r2, r3;
                ldsm_x4(r0, r1, r2, r3, stK + sw128(off));
                bh_[j2 * 2][0] = r0; bh_[j2 * 2][1] = r1;
                bh_[j2 * 2 + 1][0] = r2; bh_[j2 * 2 + 1][1] = r3;
                ldsm_x4(r0, r1, r2, r3, stK + 8192u + sw128(off));
                bl_[j2 * 2][0] = r0; bl_[j2 * 2][1] = r1;
                bl_[j2 * 2 + 1][0] = r2; bl_[j2 * 2 + 1][1] = r3;
            }
            #pragma unroll
            for (int nt = 0; nt < 8; nt++) {
                mma16816(sa[nt], qh[ks], bh_[nt]);
                mma16816(sa[nt], qh[ks], bl_[nt]);
                mma16816(sa[nt], ql[ks], bh_[nt]);
            }
        }

        // ---- scale + masks ----
        int jbase = j * 64;
        #pragma unroll
        for (int nt = 0; nt < 8; nt++) {
            int cl = nt * 8 + tig * 2;
            int kg = jbase + cl;
            int msk0 = s_mk[s][cl];
            int msk1 = s_mk[s][cl + 1];
            float v0 = sa[nt][0] * cs, v1 = sa[nt][1] * cs;
            float v2 = sa[nt][2] * cs, v3 = sa[nt][3] * cs;
            if (kg > qg0 || msk0)     v0 = -1e30f;
            if (kg + 1 > qg0 || msk1) v1 = -1e30f;
            if (kg > qg1 || msk0)     v2 = -1e30f;
            if (kg + 1 > qg1 || msk1) v3 = -1e30f;
            sa[nt][0] = v0; sa[nt][1] = v1; sa[nt][2] = v2; sa[nt][3] = v3;
        }

        // ---- online softmax ----
        float rmax0 = -1e30f, rmax1 = -1e30f;
        #pragma unroll
        for (int nt = 0; nt < 8; nt++) {
            rmax0 = fmaxf(rmax0, fmaxf(sa[nt][0], sa[nt][1]));
            rmax1 = fmaxf(rmax1, fmaxf(sa[nt][2], sa[nt][3]));
        }
        rmax0 = fmaxf(rmax0, __shfl_xor_sync(0xffffffffu, rmax0, 1));
        rmax0 = fmaxf(rmax0, __shfl_xor_sync(0xffffffffu, rmax0, 2));
        rmax1 = fmaxf(rmax1, __shfl_xor_sync(0xffffffffu, rmax1, 1));
        rmax1 = fmaxf(rmax1, __shfl_xor_sync(0xffffffffu, rmax1, 2));
        float mn0 = fmaxf(m0, rmax0), mn1 = fmaxf(m1, rmax1);
        float f0 = exp2f(m0 - mn0), f1 = exp2f(m1 - mn1);
        float ps0 = 0.f, ps1 = 0.f;
        #pragma unroll
        for (int nt = 0; nt < 8; nt++) {
            float p0 = exp2f(sa[nt][0] - mn0);
            float p1 = exp2f(sa[nt][1] - mn0);
            float p2 = exp2f(sa[nt][2] - mn1);
            float p3 = exp2f(sa[nt][3] - mn1);
            ps0 += p0 + p1; ps1 += p2 + p3;
            sa[nt][0] = p0; sa[nt][1] = p1; sa[nt][2] = p2; sa[nt][3] = p3;
        }
        ps0 += __shfl_xor_sync(0xffffffffu, ps0, 1);
        ps0 += __shfl_xor_sync(0xffffffffu, ps0, 2);
        ps1 += __shfl_xor_sync(0xffffffffu, ps1, 1);
        ps1 += __shfl_xor_sync(0xffffffffu, ps1, 2);
        l0 = l0 * f0 + ps0; m0 = mn0;
        l1 = l1 * f1 + ps1; m1 = mn1;
        #pragma unroll
        for (int nt = 0; nt < 8; nt++) {
            o[nt][0] *= f0; o[nt][1] *= f0;
            o[nt][2] *= f1; o[nt][3] *= f1;
        }

        // ---- repack P to bf16 hi/lo A-fragments ----
        uint32_t phi[4][4], plo[4][4];
        #pragma unroll
        for (int ks = 0; ks < 4; ks++) {
            split2(sa[2 * ks][0],     sa[2 * ks][1],     phi[ks][0], plo[ks][0]);
            split2(sa[2 * ks][2],     sa[2 * ks][3],     phi[ks][1], plo[ks][1]);
            split2(sa[2 * ks + 1][0], sa[2 * ks + 1][1], phi[ks][2], plo[ks][2]);
            split2(sa[2 * ks + 1][2], sa[2 * ks + 1][3], phi[ks][3], plo[ks][3]);
        }

        // ---- O += P V (3-term split, V via trans ldmatrix) ----
        #pragma unroll
        for (int ks = 0; ks < 4; ks++) {
            int vrow = ks * 16 + vRowL;
            uint32_t vh_[8][2], vl_[8][2];
            #pragma unroll
            for (int g = 0; g < 4; g++) {
                uint32_t off = (uint32_t)(vrow * 128 + g * 32 + vHalf * 16);
                uint32_t r0, r1, r2, r3;
                ldsm_x4t(r0, r1, r2, r3, stV + sw128(off));
                vh_[g * 2][0] = r0; vh_[g * 2][1] = r1;
                vh_[g * 2 + 1][0] = r2; vh_[g * 2 + 1][1] = r3;
                ldsm_x4t(r0, r1, r2, r3, stV + 8192u + sw128(off));
                vl_[g * 2][0] = r0; vl_[g * 2][1] = r1;
                vl_[g * 2 + 1][0] = r2; vl_[g * 2 + 1][1] = r3;
            }
            #pragma unroll
            for (int nt = 0; nt < 8; nt++) {
                mma16816(o[nt], phi[ks], vh_[nt]);
                mma16816(o[nt], phi[ks], vl_[nt]);
                mma16816(o[nt], plo[ks], vh_[nt]);
            }
        }

        __syncthreads();
        if (j + 2 < ntiles) { issue(j + 2, s); issued++; }
    }

    // ---- epilogue ----
    float inv0 = 1.0f / l0, inv1 = 1.0f / l1;
    #pragma unroll
    for (int nt = 0; nt < 8; nt++) {
        int d = nt * 8 + tig * 2;
        int col = h * HDIM + d;
        float2 w0; w0.x = o[nt][0] * inv0; w0.y = o[nt][1] * inv0;
        float2 w1; w1.x = o[nt][2] * inv1; w1.y = o[nt][3] * inv1;
        *(float2*)(g_att + ((size_t)b * LL + qg0) * DD + col) = w0;
        *(float2*)(g_att + ((size_t)b * LL + qg1) * DD + col) = w1;
    }
}

// ---------------- launch ----------------
extern "C" void kernel_launch(void* const* d_in, const int* in_sizes, int n_in,
                              void* d_out, int out_size) {
    const float* x  = (const float*)d_in[0];
    const unsigned char* pm = (const unsigned char*)d_in[1];
    const float* Wq = (const float*)d_in[3];
    const float* bq = (const float*)d_in[4];
    const float* Wk = (const float*)d_in[5];
    const float* bk = (const float*)d_in[6];
    const float* Wv = (const float*)d_in[7];
    const float* bv = (const float*)d_in[8];
    const float* Wo = (const float*)d_in[9];
    const float* bo = (const float*)d_in[10];
    const float* g_pre = (const float*)d_in[11];
    const float* b_pre = (const float*)d_in[12];
    const float* g_ln  = (const float*)d_in[13];
    const float* b_ln  = (const float*)d_in[14];
    float* out = (float*)d_out;

    float *ph, *patt, *py;
    __nv_bfloat16 *phHi, *phLo, *paHi, *paLo, *pwHi, *pwLo;
    __nv_bfloat16 *pqHi, *pqLo, *pkHi, *pkLo, *pvHi, *pvLo;
    cudaGetSymbolAddress((void**)&ph,   g_h);
    cudaGetSymbolAddress((void**)&patt, g_att);
    cudaGetSymbolAddress((void**)&py,   g_y);
    cudaGetSymbolAddress((void**)&phHi, g_hHi);
    cudaGetSymbolAddress((void**)&phLo, g_hLo);
    cudaGetSymbolAddress((void**)&paHi, g_aHi);
    cudaGetSymbolAddress((void**)&paLo, g_aLo);
    cudaGetSymbolAddress((void**)&pwHi, g_wHi);
    cudaGetSymbolAddress((void**)&pwLo, g_wLo);
    cudaGetSymbolAddress((void**)&pqHi, g_qHi);
    cudaGetSymbolAddress((void**)&pqLo, g_qLo);
    cudaGetSymbolAddress((void**)&pkHi, g_kHi);
    cudaGetSymbolAddress((void**)&pkLo, g_kLo);
    cudaGetSymbolAddress((void**)&pvHi, g_vHi);
    cudaGetSymbolAddress((void**)&pvLo, g_vLo);

    cudaFuncSetAttribute(gemm_mma<0>, cudaFuncAttributeMaxDynamicSharedMemorySize, GSMEM);
    cudaFuncSetAttribute(gemm_mma<1>, cudaFuncAttributeMaxDynamicSharedMemorySize, GSMEM);
    cudaFuncSetAttribute(attn_mma, cudaFuncAttributeMaxDynamicSharedMemorySize, ASMEM);

    convert_mask_kernel<<<1, 256>>>(pm);

    // pre-LN
    ln_kernel<<<NROWS, 256>>>(x, (const float*)nullptr, g_pre, b_pre, ph);

    const int nAct = NROWS * DD;
    const int nW   = DD * DD;
    split_kernel<<<nAct / 1024, 256>>>(ph, phHi, phLo, nAct);
    split_kernel<<<nW / 1024, 256>>>(Wq, pwHi + 0 * (size_t)nW, pwLo + 0 * (size_t)nW, nW);
    split_kernel<<<nW / 1024, 256>>>(Wk, pwHi + 1 * (size_t)nW, pwLo + 1 * (size_t)nW, nW);
    split_kernel<<<nW / 1024, 256>>>(Wv, pwHi + 2 * (size_t)nW, pwLo + 2 * (size_t)nW, nW);
    split_kernel<<<nW / 1024, 256>>>(Wo, pwHi + 3 * (size_t)nW, pwLo + 3 * (size_t)nW, nW);

    // QKV projections -> bf16 hi/lo (B,H,L,HD)
    dim3 gproj(DD / 128, NROWS / 128);
    gemm_mma<1><<<gproj, 256, GSMEM>>>(phHi, phLo, pwHi + 0 * (size_t)nW, pwLo + 0 * (size_t)nW, bq, nullptr, pqHi, pqLo);
    gemm_mma<1><<<gproj, 256, GSMEM>>>(phHi, phLo, pwHi + 1 * (size_t)nW, pwLo + 1 * (size_t)nW, bk, nullptr, pkHi, pkLo);
    gemm_mma<1><<<gproj, 256, GSMEM>>>(phHi, phLo, pwHi + 2 * (size_t)nW, pwLo + 2 * (size_t)nW, bv, nullptr, pvHi, pvLo);

    // tensor-core flash attention
    attn_mma<<<dim3(LL / 128, BB * HH), 256, ASMEM>>>();

    // output projection
    split_kernel<<<nAct / 1024, 256>>>(patt, paHi, paLo, nAct);
    gemm_mma<0><<<gproj, 256, GSMEM>>>(paHi, paLo, pwHi + 3 * (size_t)nW, pwLo + 3 * (size_t)nW, bo, py, nullptr, nullptr);

    // residual + final LN
    ln_kernel<<<NROWS, 256>>>(py, ph, g_ln, b_ln, out);
}